// round 11
// baseline (speedup 1.0000x reference)
#include <cuda_runtime.h>

// RoI max pooling with modular binning, matching the JAX reference:
//   y1 = rint(rois[1]/16); x1 = rint(rois[2]/16)
//   y2 = min(rint(rois[3]/16), h-1); x2 = min(rint(rois[4]/16), w-1)
//   bin(i,j) = max over {y = y1+i+7k <= y2, x = x1+j+7m <= x2} of x[b,c,y,x]
//   pad bins (i >= ft_h%7 != 0  or  j >= ft_w%7 != 0) get max(val, 0)

#define H_OUT 7
#define W_OUT 7
#define C_DIM 512
#define H_IN  50
#define W_IN  50
#define SCALE 0.0625f

__global__ __launch_bounds__(256)
void roi_pool_kernel(const float* __restrict__ x,
                     const float* __restrict__ rois,
                     float* __restrict__ out,
                     int total, int R) {
    int tid = blockIdx.x * blockDim.x + threadIdx.x;
    if (tid >= total) return;

    // Layout: out[r, c, i, j] with (i*7+j) fastest -> lanes j adjacent
    int bin = tid % (H_OUT * W_OUT);
    int c   = (tid / (H_OUT * W_OUT)) % C_DIM;
    int r   = tid / (H_OUT * W_OUT * C_DIM);
    int i   = bin / W_OUT;
    int j   = bin % W_OUT;

    // RoI params (warp-uniform loads -> broadcast, L1-hot)
    const float* rp = rois + r * 5;
    float f0 = __ldg(rp + 0);
    float f1 = __ldg(rp + 1);
    float f2 = __ldg(rp + 2);
    float f3 = __ldg(rp + 3);
    float f4 = __ldg(rp + 4);

    int b  = (int)f0;                       // float->int truncation (values 0/1)
    int y1 = (int)rintf(f1 * SCALE);        // rintf = round half to even (matches jnp.round)
    int x1 = (int)rintf(f2 * SCALE);
    int y2 = min((int)rintf(f3 * SCALE), H_IN - 1);
    int x2 = min((int)rintf(f4 * SCALE), W_IN - 1);

    const float* src = x + ((long long)b * C_DIM + c) * (H_IN * W_IN);

    float m = __int_as_float(0xff800000);   // -inf (segment_max identity)

    for (int y = y1 + i; y <= y2; y += H_OUT) {
        const float* row = src + y * W_IN;
        #pragma unroll 4
        for (int xx = x1 + j; xx <= x2; xx += W_OUT) {
            m = fmaxf(m, __ldg(row + xx));
        }
    }

    int ft_h  = y2 - y1 + 1;
    int ft_w  = x2 - x1 + 1;
    int rem_h = ft_h % H_OUT;
    int rem_w = ft_w % W_OUT;
    bool pad  = ((rem_h != 0) && (i >= rem_h)) || ((rem_w != 0) && (j >= rem_w));
    if (pad) m = fmaxf(m, 0.0f);

    out[tid] = m;
}

extern "C" void kernel_launch(void* const* d_in, const int* in_sizes, int n_in,
                              void* d_out, int out_size) {
    const float* x    = (const float*)d_in[0];   // (2, 512, 50, 50) f32
    const float* rois = (const float*)d_in[1];   // (128, 5) f32
    float* out        = (float*)d_out;           // (R, 512, 7, 7) f32

    int R = in_sizes[1] / 5;
    int total = R * C_DIM * H_OUT * W_OUT;
    int threads = 256;
    int blocks = (total + threads - 1) / threads;
    roi_pool_kernel<<<blocks, threads>>>(x, rois, out, total, R);
}

// round 12
// speedup vs baseline: 1.2073x; 1.2073x over previous
#include <cuda_runtime.h>

// RoI max pooling, modular binning (matches JAX reference exactly; R11 rel_err was 0):
//   y1 = rint(rois[1]/16); x1 = rint(rois[2]/16)
//   y2 = min(rint(rois[3]/16), 49); x2 = min(rint(rois[4]/16), 49)
//   bin(i,j) = max over {y = y1+i+7k <= y2, x = x1+j+7m <= x2}
//   pad bins (i >= ft_h%7 !=0 or j >= ft_w%7 !=0): max(val, 0)
//
// R11 analysis: issue/ALU-bound (alu 47.8%, issue 69.5%, DRAM 5%). This version
// removes per-thread roi float math (init kernel), index div/mod (3D block),
// and loop branches (4x4 fully-unrolled predicated taps; dy,dx <= 25 always).

#define H_OUT 7
#define W_OUT 7
#define C_DIM 512
#define H_IN  50
#define W_IN  50
#define HW_IN (H_IN * W_IN)
#define R_MAX 128
#define CPB   8      // channels per block -> blockDim = 7*7*8 = 392

struct __align__(16) RoiParam {
    int base;                 // b*C*HW + y1*W + x1
    int dy;                   // y2 - y1   (<= 25)
    int dx;                   // x2 - x1   (<= 25)
    int _pad;
    unsigned long long mask;  // bit(i*7+j) set => pad-clamp this bin
    unsigned long long _pad2;
};

__device__ RoiParam g_params[R_MAX];

__global__ void init_params(const float* __restrict__ rois, int R) {
    int r = threadIdx.x + blockIdx.x * blockDim.x;
    if (r >= R) return;
    const float* rp = rois + r * 5;
    int b  = (int)rp[0];
    int y1 = (int)rintf(rp[1] * 0.0625f);   // rintf = round half-even (jnp.round)
    int x1 = (int)rintf(rp[2] * 0.0625f);
    int y2 = min((int)rintf(rp[3] * 0.0625f), H_IN - 1);
    int x2 = min((int)rintf(rp[4] * 0.0625f), W_IN - 1);
    int dy = y2 - y1, dx = x2 - x1;
    int rem_h = (dy + 1) % H_OUT;
    int rem_w = (dx + 1) % W_OUT;
    unsigned long long mask = 0ull;
    for (int i = 0; i < H_OUT; i++)
        for (int j = 0; j < W_OUT; j++) {
            bool pad = ((rem_h != 0) && (i >= rem_h)) || ((rem_w != 0) && (j >= rem_w));
            if (pad) mask |= 1ull << (i * W_OUT + j);
        }
    RoiParam p;
    p.base = b * (C_DIM * HW_IN) + y1 * W_IN + x1;
    p.dy = dy; p.dx = dx; p._pad = 0;
    p.mask = mask; p._pad2 = 0ull;
    g_params[r] = p;
}

__global__ __launch_bounds__(7 * 7 * CPB)
void roi_pool_main(const float* __restrict__ x, float* __restrict__ out) {
    const int j = threadIdx.x;                      // 0..6
    const int i = threadIdx.y;                      // 0..6
    const int c = blockIdx.x * CPB + threadIdx.z;   // channel
    const int r = blockIdx.y;                       // roi

    // warp-uniform param load (L1-hot after first warp of the block)
    const RoiParam p = g_params[r];

    const float* src = x + p.base + c * HW_IN + i * W_IN + j;

    float m = __int_as_float(0xff800000);           // -inf (segment_max identity)

    // dy,dx <= 25 => at most 4 taps per axis. Fully unrolled, predicated,
    // immediate offsets -> 16 independent @P LDG (MLP=16), zero branches.
    #pragma unroll
    for (int ky = 0; ky < 4; ky++) {
        if (i + 7 * ky <= p.dy) {
            #pragma unroll
            for (int kx = 0; kx < 4; kx++) {
                if (j + 7 * kx <= p.dx)
                    m = fmaxf(m, __ldg(src + ky * (7 * W_IN) + kx * 7));
            }
        }
    }

    const int bin = i * W_OUT + j;
    if ((p.mask >> bin) & 1ull) m = fmaxf(m, 0.0f);

    out[(r * C_DIM + c) * (H_OUT * W_OUT) + bin] = m;
}

extern "C" void kernel_launch(void* const* d_in, const int* in_sizes, int n_in,
                              void* d_out, int out_size) {
    const float* x    = (const float*)d_in[0];   // (2, 512, 50, 50) f32
    const float* rois = (const float*)d_in[1];   // (R, 5) f32
    float* out        = (float*)d_out;           // (R, 512, 7, 7) f32

    int R = in_sizes[1] / 5;                     // 128

    init_params<<<(R + 127) / 128, 128>>>(rois, R);

    dim3 block(W_OUT, H_OUT, CPB);               // 7 x 7 x 8 = 392 threads
    dim3 grid(C_DIM / CPB, R);                   // 64 x 128 blocks
    roi_pool_main<<<grid, block>>>(x, out);
}

// round 13
// speedup vs baseline: 1.3401x; 1.1100x over previous
#include <cuda_runtime.h>

// RoI max pooling, modular binning (rel_err == 0 in R11/R12 with identical math):
//   y1 = rint(rois[1]/16); x1 = rint(rois[2]/16)
//   y2 = min(rint(rois[3]/16), 49); x2 = min(rint(rois[4]/16), 49)
//   bin(i,j) = max over {y = y1+i+7k <= y2, x = x1+j+7m <= x2}
//   pad bins (i >= ft_h%7 !=0 or j >= ft_w%7 !=0): max(val, 0)
//
// R12 analysis: nothing saturated (L1 41%, issue 47%, occ 67%) -> latency-bound.
// R13: 2 channels per thread (two independent 16-tap fmax chains, 32-deep MLP),
// params computed per-block into smem (init kernel merged away).

#define H_OUT 7
#define W_OUT 7
#define C_DIM 512
#define H_IN  50
#define W_IN  50
#define HW_IN (H_IN * W_IN)
#define CPB   8      // threadIdx.z extent; each thread does channels c and c+CPB
#define CPT   2      // channels per thread
#define CPBLK (CPB * CPT)   // 16 channels per block

struct RoiParam {
    int base;                 // b*C*HW + y1*W + x1
    int dy;                   // y2 - y1  (<= 25)
    int dx;                   // x2 - x1  (<= 25)
    unsigned long long mask;  // bit(i*7+j) set => pad-clamp this bin
};

__global__ __launch_bounds__(7 * 7 * CPB, 3)
void roi_pool_fused(const float* __restrict__ x,
                    const float* __restrict__ rois,
                    float* __restrict__ out) {
    const int j  = threadIdx.x;                       // 0..6
    const int i  = threadIdx.y;                       // 0..6
    const int c0 = blockIdx.x * CPBLK + threadIdx.z;  // first channel
    const int r  = blockIdx.y;                        // roi

    __shared__ RoiParam sp;

    if (threadIdx.x == 0 && threadIdx.y == 0 && threadIdx.z == 0) {
        const float* rp = rois + r * 5;
        int b  = (int)rp[0];
        int y1 = (int)rintf(rp[1] * 0.0625f);   // rintf = round half-even (jnp.round)
        int x1 = (int)rintf(rp[2] * 0.0625f);
        int y2 = min((int)rintf(rp[3] * 0.0625f), H_IN - 1);
        int x2 = min((int)rintf(rp[4] * 0.0625f), W_IN - 1);
        int dy = y2 - y1, dx = x2 - x1;
        int rem_h = (dy + 1) % H_OUT;
        int rem_w = (dx + 1) % W_OUT;
        unsigned long long mask = 0ull;
        #pragma unroll
        for (int ii = 0; ii < H_OUT; ii++)
            #pragma unroll
            for (int jj = 0; jj < W_OUT; jj++) {
                bool pad = ((rem_h != 0) && (ii >= rem_h)) ||
                           ((rem_w != 0) && (jj >= rem_w));
                if (pad) mask |= 1ull << (ii * W_OUT + jj);
            }
        sp.base = b * (C_DIM * HW_IN) + y1 * W_IN + x1;
        sp.dy = dy; sp.dx = dx; sp.mask = mask;
    }
    __syncthreads();

    const int   dy   = sp.dy;
    const int   dx   = sp.dx;
    const float* s0  = x + sp.base + c0 * HW_IN + i * W_IN + j;
    const float* s1  = s0 + CPB * HW_IN;

    const float NEG_INF = __int_as_float(0xff800000);
    float m0 = NEG_INF, m1 = NEG_INF;

    // dy,dx <= 25 => at most 4 taps per axis. Fully unrolled, predicated,
    // two independent chains -> up to 32 LDGs in flight.
    #pragma unroll
    for (int ky = 0; ky < 4; ky++) {
        const bool rowok = (i + 7 * ky <= dy);
        #pragma unroll
        for (int kx = 0; kx < 4; kx++) {
            if (rowok && (j + 7 * kx <= dx)) {
                const int off = ky * (7 * W_IN) + kx * 7;
                m0 = fmaxf(m0, __ldg(s0 + off));
                m1 = fmaxf(m1, __ldg(s1 + off));
            }
        }
    }

    const int bin = i * W_OUT + j;
    if ((sp.mask >> bin) & 1ull) {
        m0 = fmaxf(m0, 0.0f);
        m1 = fmaxf(m1, 0.0f);
    }

    float* o0 = out + ((long long)r * C_DIM + c0) * (H_OUT * W_OUT) + bin;
    o0[0] = m0;
    o0[CPB * H_OUT * W_OUT] = m1;
}

extern "C" void kernel_launch(void* const* d_in, const int* in_sizes, int n_in,
                              void* d_out, int out_size) {
    const float* x    = (const float*)d_in[0];   // (2, 512, 50, 50) f32
    const float* rois = (const float*)d_in[1];   // (R, 5) f32
    float* out        = (float*)d_out;           // (R, 512, 7, 7) f32

    int R = in_sizes[1] / 5;                     // 128

    dim3 block(W_OUT, H_OUT, CPB);               // 7 x 7 x 8 = 392 threads
    dim3 grid(C_DIM / CPBLK, R);                 // 32 x 128 = 4096 blocks
    roi_pool_fused<<<grid, block>>>(x, rois, out);
}

// round 14
// speedup vs baseline: 1.5000x; 1.1193x over previous
#include <cuda_runtime.h>

// RoI max pooling, modular binning (rel_err == 0 since R11 with identical math):
//   y1 = rint(rois[1]/16); x1 = rint(rois[2]/16)
//   y2 = min(rint(rois[3]/16), 49); x2 = min(rint(rois[4]/16), 49)
//   bin(i,j) = max over {y = y1+i+7k <= y2, x = x1+j+7m <= x2}
//   pad bins (i >= ft_h%7 !=0 or j >= ft_w%7 !=0): max(val, 0)
//
// R13 analysis: latency-bound (L1 51%, issue 45%, DRAM 7% -- nothing saturated).
// R14: 4 channels/thread -> 64-deep LDG MLP via one base reg + immediate offsets;
// pad predicate computed per-thread (no serial mask build, no 64-bit mask).

#define H_OUT 7
#define W_OUT 7
#define C_DIM 512
#define H_IN  50
#define W_IN  50
#define HW_IN (H_IN * W_IN)
#define CPB   8                 // threadIdx.z extent
#define CPT   4                 // channels per thread
#define CPBLK (CPB * CPT)       // 32 channels per block

__global__ __launch_bounds__(7 * 7 * CPB, 3)
void roi_pool_fused(const float* __restrict__ x,
                    const float* __restrict__ rois,
                    float* __restrict__ out) {
    const int j  = threadIdx.x;                       // 0..6
    const int i  = threadIdx.y;                       // 0..6
    const int c0 = blockIdx.x * CPBLK + threadIdx.z;  // first channel
    const int r  = blockIdx.y;                        // roi

    __shared__ int s_base, s_dy, s_dx;

    if (threadIdx.x == 0 && threadIdx.y == 0 && threadIdx.z == 0) {
        const float* rp = rois + r * 5;
        int b  = (int)rp[0];
        int y1 = (int)rintf(rp[1] * 0.0625f);   // rintf = round half-even (jnp.round)
        int x1 = (int)rintf(rp[2] * 0.0625f);
        int y2 = min((int)rintf(rp[3] * 0.0625f), H_IN - 1);
        int x2 = min((int)rintf(rp[4] * 0.0625f), W_IN - 1);
        s_base = b * (C_DIM * HW_IN) + y1 * W_IN + x1;
        s_dy = y2 - y1;
        s_dx = x2 - x1;
    }
    __syncthreads();

    const int dy = s_dy;
    const int dx = s_dx;
    const float* src = x + s_base + c0 * HW_IN + i * W_IN + j;

    const float NEG_INF = __int_as_float(0xff800000);
    float m0 = NEG_INF, m1 = NEG_INF, m2 = NEG_INF, m3 = NEG_INF;

    // dy,dx <= 25 => at most 4 taps per axis. Fully unrolled, predicated,
    // 4 independent chains, all offsets compile-time immediates off one base.
    #pragma unroll
    for (int ky = 0; ky < 4; ky++) {
        const bool rowok = (i + 7 * ky <= dy);
        #pragma unroll
        for (int kx = 0; kx < 4; kx++) {
            if (rowok && (j + 7 * kx <= dx)) {
                const int off = ky * (7 * W_IN) + kx * 7;
                m0 = fmaxf(m0, __ldg(src + off));
                m1 = fmaxf(m1, __ldg(src + off +      CPB * HW_IN));
                m2 = fmaxf(m2, __ldg(src + off +  2 * CPB * HW_IN));
                m3 = fmaxf(m3, __ldg(src + off +  3 * CPB * HW_IN));
            }
        }
    }

    // pad-clamp: bins at/after the remainder row/col get max(val, 0)
    const int rem_h = (dy + 1) % H_OUT;
    const int rem_w = (dx + 1) % W_OUT;
    const bool pad = ((rem_h != 0) && (i >= rem_h)) ||
                     ((rem_w != 0) && (j >= rem_w));
    if (pad) {
        m0 = fmaxf(m0, 0.0f);
        m1 = fmaxf(m1, 0.0f);
        m2 = fmaxf(m2, 0.0f);
        m3 = fmaxf(m3, 0.0f);
    }

    const int bin = i * W_OUT + j;
    float* o = out + ((long long)r * C_DIM + c0) * (H_OUT * W_OUT) + bin;
    o[0]                        = m0;
    o[    CPB * H_OUT * W_OUT]  = m1;
    o[2 * CPB * H_OUT * W_OUT]  = m2;
    o[3 * CPB * H_OUT * W_OUT]  = m3;
}

extern "C" void kernel_launch(void* const* d_in, const int* in_sizes, int n_in,
                              void* d_out, int out_size) {
    const float* x    = (const float*)d_in[0];   // (2, 512, 50, 50) f32
    const float* rois = (const float*)d_in[1];   // (R, 5) f32
    float* out        = (float*)d_out;           // (R, 512, 7, 7) f32

    int R = in_sizes[1] / 5;                     // 128

    dim3 block(W_OUT, H_OUT, CPB);               // 7 x 7 x 8 = 392 threads
    dim3 grid(C_DIM / CPBLK, R);                 // 16 x 128 = 2048 blocks
    roi_pool_fused<<<grid, block>>>(x, rois, out);
}